// round 1
// baseline (speedup 1.0000x reference)
#include <cuda_runtime.h>
#include <cuda_bf16.h>
#include <cstdint>
#include <cstdio>

#define HID   1024
#define CDIM  1024
#define NHEAD 16
#define HDIM  64
#define LSEQ  2048
#define BATCH 2
#define MTOT  4096   // B*L
#define MLPD  4096

// ---------------- scratch (static device globals; no cudaMalloc allowed) ---
__device__ float g_normed[MTOT * HID];
__device__ float g_q[MTOT * HID];
__device__ float g_k[MTOT * HID];
__device__ float g_v[MTOT * HID];
__device__ float g_attn[MTOT * HID];
__device__ float g_h[MTOT * MLPD];
__device__ float g_ss[2 * BATCH * 2048];   // [layer][batch][2H]

// ---------------- helpers --------------------------------------------------
__device__ __forceinline__ float tf32r(float x) {
    uint32_t u;
    asm("cvt.rna.tf32.f32 %0, %1;" : "=r"(u) : "f"(x));
    return __uint_as_float(u);
}

__device__ __forceinline__ void mma8(float* d, const uint32_t* a, const uint32_t* b) {
    asm volatile(
        "mma.sync.aligned.m16n8k8.row.col.f32.tf32.tf32.f32 "
        "{%0,%1,%2,%3}, {%4,%5,%6,%7}, {%8,%9}, {%0,%1,%2,%3};\n"
        : "+f"(d[0]), "+f"(d[1]), "+f"(d[2]), "+f"(d[3])
        : "r"(a[0]), "r"(a[1]), "r"(a[2]), "r"(a[3]), "r"(b[0]), "r"(b[1]));
}

// ---------------- adaLN modulation: ss = cond @ W^T + b  (tiny) ------------
__global__ void __launch_bounds__(256) ss_kernel(
    const float* __restrict__ cond,
    const float* __restrict__ w1, const float* __restrict__ b1,
    const float* __restrict__ w2, const float* __restrict__ b2,
    float* __restrict__ ss)
{
    int warp = threadIdx.x >> 5, lane = threadIdx.x & 31;
    int gw = blockIdx.x * 8 + warp;           // 0..8191
    int layer = gw >> 12;
    int rem = gw & 4095;
    int b = rem >> 11;
    int row = rem & 2047;
    const float* W  = layer ? w2 : w1;
    const float* bv = layer ? b2 : b1;
    const float* c  = cond + b * CDIM;
    const float* wr = W + (size_t)row * CDIM;
    float s = 0.f;
    for (int k = lane; k < CDIM; k += 32) s += c[k] * wr[k];
    #pragma unroll
    for (int o = 16; o > 0; o >>= 1) s += __shfl_xor_sync(0xffffffffu, s, o);
    if (lane == 0) ss[layer * (BATCH * 2048) + b * 2048 + row] = s + bv[row];
}

// ---------------- LayerNorm * (1+scale) + shift ----------------------------
__global__ void __launch_bounds__(256) adaln_kernel(
    const float* __restrict__ x, const float* __restrict__ ss,
    float* __restrict__ out)
{
    int row = blockIdx.x;
    int b = row >> 11;
    const float* xr = x + (size_t)row * HID;
    float v[4];
    float s = 0.f, sq = 0.f;
    #pragma unroll
    for (int i = 0; i < 4; i++) {
        v[i] = xr[threadIdx.x + i * 256];
        s += v[i];
        sq += v[i] * v[i];
    }
    __shared__ float red[16];
    #pragma unroll
    for (int o = 16; o > 0; o >>= 1) {
        s  += __shfl_xor_sync(0xffffffffu, s,  o);
        sq += __shfl_xor_sync(0xffffffffu, sq, o);
    }
    int warp = threadIdx.x >> 5, lane = threadIdx.x & 31;
    if (lane == 0) { red[warp] = s; red[warp + 8] = sq; }
    __syncthreads();
    if (warp == 0) {
        float a  = lane < 8 ? red[lane] : 0.f;
        float c2 = lane < 8 ? red[lane + 8] : 0.f;
        #pragma unroll
        for (int o = 4; o > 0; o >>= 1) {
            a  += __shfl_xor_sync(0xffffffffu, a,  o);
            c2 += __shfl_xor_sync(0xffffffffu, c2, o);
        }
        if (lane == 0) { red[0] = a; red[1] = c2; }
    }
    __syncthreads();
    float mean = red[0] * (1.f / HID);
    float var  = red[1] * (1.f / HID) - mean * mean;
    float rs   = rsqrtf(var + 1e-5f);
    const float* sc = ss + b * 2048;
    #pragma unroll
    for (int i = 0; i < 4; i++) {
        int c = threadIdx.x + i * 256;
        out[(size_t)row * HID + c] = (v[i] - mean) * rs * (1.f + sc[c]) + sc[1024 + c];
    }
}

// ---------------- generic TF32 GEMM: C = A @ B^T + bias (+resid)(gelu) -----
// A [M,K] row-major, B [N,K] row-major (i.e., weight W), C [M,N].
// BM=BN=128, BK=32. 256 threads = 8 warps as 4x2; warp tile 32x64.
template <bool GELU, bool RESID>
__global__ void __launch_bounds__(256) gemm_kernel(
    const float* __restrict__ A, const float* __restrict__ B,
    const float* __restrict__ bias, const float* __restrict__ R,
    float* __restrict__ C, int M, int N, int K)
{
    __shared__ float As[128][36];
    __shared__ float Bs[128][36];
    int tid = threadIdx.x, warp = tid >> 5, lane = tid & 31;
    int wm = (warp >> 1) * 32, wn = (warp & 1) * 64;
    int bm = blockIdx.y * 128, bn = blockIdx.x * 128;

    float acc[2][8][4];
    #pragma unroll
    for (int i = 0; i < 2; i++)
        #pragma unroll
        for (int j = 0; j < 8; j++)
            #pragma unroll
            for (int e = 0; e < 4; e++) acc[i][j][e] = 0.f;

    int lr = tid >> 3;          // 0..31
    int lc = (tid & 7) * 4;     // 0..28
    const float* Ag = A + (size_t)(bm + lr) * K + lc;
    const float* Bg = B + (size_t)(bn + lr) * K + lc;

    for (int k0 = 0; k0 < K; k0 += 32) {
        #pragma unroll
        for (int i = 0; i < 4; i++) {
            float4 av = *(const float4*)(Ag + (size_t)(i * 32) * K + k0);
            float4 bv = *(const float4*)(Bg + (size_t)(i * 32) * K + k0);
            av.x = tf32r(av.x); av.y = tf32r(av.y); av.z = tf32r(av.z); av.w = tf32r(av.w);
            bv.x = tf32r(bv.x); bv.y = tf32r(bv.y); bv.z = tf32r(bv.z); bv.w = tf32r(bv.w);
            *(float4*)&As[lr + i * 32][lc] = av;
            *(float4*)&Bs[lr + i * 32][lc] = bv;
        }
        __syncthreads();
        #pragma unroll
        for (int ks = 0; ks < 4; ks++) {
            int c = ks * 8 + (lane & 3);
            uint32_t af[2][4];
            #pragma unroll
            for (int mt = 0; mt < 2; mt++) {
                int r = wm + mt * 16 + (lane >> 2);
                af[mt][0] = __float_as_uint(As[r][c]);
                af[mt][1] = __float_as_uint(As[r + 8][c]);
                af[mt][2] = __float_as_uint(As[r][c + 4]);
                af[mt][3] = __float_as_uint(As[r + 8][c + 4]);
            }
            #pragma unroll
            for (int nt = 0; nt < 8; nt++) {
                int n = wn + nt * 8 + (lane >> 2);
                uint32_t bf[2];
                bf[0] = __float_as_uint(Bs[n][c]);
                bf[1] = __float_as_uint(Bs[n][c + 4]);
                mma8(acc[0][nt], af[0], bf);
                mma8(acc[1][nt], af[1], bf);
            }
        }
        __syncthreads();
    }

    #pragma unroll
    for (int mt = 0; mt < 2; mt++) {
        int r0 = bm + wm + mt * 16 + (lane >> 2);
        #pragma unroll
        for (int nt = 0; nt < 8; nt++) {
            int cn = bn + wn + nt * 8 + (lane & 3) * 2;
            #pragma unroll
            for (int e = 0; e < 4; e++) {
                int r  = r0 + (e >= 2 ? 8 : 0);
                int cc = cn + (e & 1);
                float vv = acc[mt][nt][e] + bias[cc];
                if (RESID) vv += R[(size_t)r * N + cc];
                if (GELU)  vv = 0.5f * vv * (1.f + erff(vv * 0.70710678118f));
                C[(size_t)r * N + cc] = vv;
            }
        }
    }
}

// ---------------- flash attention ------------------------------------------
// grid (L/128, NH, B). 256 threads = 8 warps, each warp owns 16 q rows.
#define QS_STR 68
#define VS_STR 72
#define PS_STR 132
#define FA_SMEM ((128 * QS_STR + 128 * QS_STR + 128 * VS_STR + 128 * PS_STR + 128) * 4)

__global__ void __launch_bounds__(256) flash_kernel(
    const float* __restrict__ Q, const float* __restrict__ Kb,
    const float* __restrict__ Vb, const unsigned char* __restrict__ msk,
    float* __restrict__ O)
{
    extern __shared__ float sm[];
    float* Qs = sm;                        // [128][68]
    float* Ks = Qs + 128 * QS_STR;         // [128][68]
    float* Vs = Ks + 128 * QS_STR;         // [128][72]
    float* Ps = Vs + 128 * VS_STR;         // [128][132]
    float* Mb = Ps + 128 * PS_STR;         // [128] mask bias
    int qb = blockIdx.x, h = blockIdx.y, b = blockIdx.z;
    int tid = threadIdx.x, warp = tid >> 5, lane = tid & 31;

    size_t base_q = ((size_t)(b * LSEQ + qb * 128)) * HID + h * HDIM;
    #pragma unroll
    for (int i = 0; i < 8; i++) {
        int idx = tid + i * 256;
        int row = idx >> 4, c4 = (idx & 15) * 4;
        float4 qv = *(const float4*)(Q + base_q + (size_t)row * HID + c4);
        qv.x = tf32r(qv.x); qv.y = tf32r(qv.y); qv.z = tf32r(qv.z); qv.w = tf32r(qv.w);
        *(float4*)&Qs[row * QS_STR + c4] = qv;
    }

    float Oacc[8][4];
    #pragma unroll
    for (int i = 0; i < 8; i++)
        #pragma unroll
        for (int e = 0; e < 4; e++) Oacc[i][e] = 0.f;
    float mrow[2] = {-1e30f, -1e30f}, lrow[2] = {0.f, 0.f};

    for (int kb = 0; kb < LSEQ / 128; kb++) {
        size_t base_k = ((size_t)(b * LSEQ + kb * 128)) * HID + h * HDIM;
        #pragma unroll
        for (int i = 0; i < 8; i++) {
            int idx = tid + i * 256;
            int row = idx >> 4, c4 = (idx & 15) * 4;
            float4 kv = *(const float4*)(Kb + base_k + (size_t)row * HID + c4);
            float4 vv = *(const float4*)(Vb + base_k + (size_t)row * HID + c4);
            kv.x = tf32r(kv.x); kv.y = tf32r(kv.y); kv.z = tf32r(kv.z); kv.w = tf32r(kv.w);
            vv.x = tf32r(vv.x); vv.y = tf32r(vv.y); vv.z = tf32r(vv.z); vv.w = tf32r(vv.w);
            *(float4*)&Ks[row * QS_STR + c4] = kv;
            *(float4*)&Vs[row * VS_STR + c4] = vv;
        }
        if (tid < 128) Mb[tid] = msk[b * LSEQ + kb * 128 + tid] ? -1e30f : 0.f;
        __syncthreads();

        // S = Q @ K^T  (warp: 16 x 128)
        float sacc[16][4];
        #pragma unroll
        for (int i = 0; i < 16; i++)
            #pragma unroll
            for (int e = 0; e < 4; e++) sacc[i][e] = 0.f;

        #pragma unroll
        for (int ks = 0; ks < 8; ks++) {
            int c = ks * 8 + (lane & 3);
            int r = warp * 16 + (lane >> 2);
            uint32_t af[4];
            af[0] = __float_as_uint(Qs[r * QS_STR + c]);
            af[1] = __float_as_uint(Qs[(r + 8) * QS_STR + c]);
            af[2] = __float_as_uint(Qs[r * QS_STR + c + 4]);
            af[3] = __float_as_uint(Qs[(r + 8) * QS_STR + c + 4]);
            #pragma unroll
            for (int nt = 0; nt < 16; nt++) {
                int n = nt * 8 + (lane >> 2);
                uint32_t bf[2];
                bf[0] = __float_as_uint(Ks[n * QS_STR + c]);
                bf[1] = __float_as_uint(Ks[n * QS_STR + c + 4]);
                mma8(sacc[nt], af, bf);
            }
        }

        // online softmax per row (j=0: row r, j=1: row r+8)
        #pragma unroll
        for (int j = 0; j < 2; j++) {
            float tmax = -1e30f;
            #pragma unroll
            for (int nt = 0; nt < 16; nt++) {
                #pragma unroll
                for (int e = 0; e < 2; e++) {
                    int kc = nt * 8 + (lane & 3) * 2 + e;
                    float sv = sacc[nt][j * 2 + e] * 0.125f + Mb[kc];
                    sacc[nt][j * 2 + e] = sv;
                    tmax = fmaxf(tmax, sv);
                }
            }
            tmax = fmaxf(tmax, __shfl_xor_sync(0xffffffffu, tmax, 1));
            tmax = fmaxf(tmax, __shfl_xor_sync(0xffffffffu, tmax, 2));
            float mnew  = fmaxf(mrow[j], tmax);
            float alpha = __expf(mrow[j] - mnew);
            mrow[j] = mnew;
            float psum = 0.f;
            int rl = warp * 16 + (lane >> 2) + j * 8;
            #pragma unroll
            for (int nt = 0; nt < 16; nt++) {
                #pragma unroll
                for (int e = 0; e < 2; e++) {
                    float p = __expf(sacc[nt][j * 2 + e] - mnew);
                    psum += p;
                    Ps[rl * PS_STR + nt * 8 + (lane & 3) * 2 + e] = tf32r(p);
                }
            }
            psum += __shfl_xor_sync(0xffffffffu, psum, 1);
            psum += __shfl_xor_sync(0xffffffffu, psum, 2);
            lrow[j] = lrow[j] * alpha + psum;
            #pragma unroll
            for (int nt = 0; nt < 8; nt++) {
                Oacc[nt][j * 2]     *= alpha;
                Oacc[nt][j * 2 + 1] *= alpha;
            }
        }
        __syncwarp();

        // O += P @ V  (warp: 16 x 64, K=128)
        #pragma unroll
        for (int ks = 0; ks < 16; ks++) {
            int c = ks * 8 + (lane & 3);
            int r = warp * 16 + (lane >> 2);
            uint32_t af[4];
            af[0] = __float_as_uint(Ps[r * PS_STR + c]);
            af[1] = __float_as_uint(Ps[(r + 8) * PS_STR + c]);
            af[2] = __float_as_uint(Ps[r * PS_STR + c + 4]);
            af[3] = __float_as_uint(Ps[(r + 8) * PS_STR + c + 4]);
            #pragma unroll
            for (int nt = 0; nt < 8; nt++) {
                uint32_t bf[2];
                bf[0] = __float_as_uint(Vs[c * VS_STR + nt * 8 + (lane >> 2)]);
                bf[1] = __float_as_uint(Vs[(c + 4) * VS_STR + nt * 8 + (lane >> 2)]);
                mma8(Oacc[nt], af, bf);
            }
        }
        __syncthreads();
    }

    #pragma unroll
    for (int j = 0; j < 2; j++) {
        float inv = 1.f / lrow[j];
        int row = qb * 128 + warp * 16 + (lane >> 2) + j * 8;
        size_t ob = ((size_t)(b * LSEQ + row)) * HID + h * HDIM;
        #pragma unroll
        for (int nt = 0; nt < 8; nt++) {
            int cc = nt * 8 + (lane & 3) * 2;
            O[ob + cc]     = Oacc[nt][j * 2] * inv;
            O[ob + cc + 1] = Oacc[nt][j * 2 + 1] * inv;
        }
    }
}

// ---------------- launch ----------------------------------------------------
extern "C" void kernel_launch(void* const* d_in, const int* in_sizes, int n_in,
                              void* d_out, int out_size)
{
    const float* x    = (const float*)d_in[0];
    const float* cond = (const float*)d_in[1];
    const unsigned char* kpm = (const unsigned char*)d_in[2];
    const float* w_ad1 = (const float*)d_in[3];
    const float* b_ad1 = (const float*)d_in[4];
    const float* w_ad2 = (const float*)d_in[5];
    const float* b_ad2 = (const float*)d_in[6];
    const float* wq = (const float*)d_in[7];
    const float* bq = (const float*)d_in[8];
    const float* wk = (const float*)d_in[9];
    const float* bk = (const float*)d_in[10];
    const float* wv = (const float*)d_in[11];
    const float* bv = (const float*)d_in[12];
    const float* wo = (const float*)d_in[13];
    const float* bo = (const float*)d_in[14];
    const float* w1 = (const float*)d_in[15];
    const float* b1 = (const float*)d_in[16];
    const float* w2 = (const float*)d_in[17];
    const float* b2 = (const float*)d_in[18];
    float* out = (float*)d_out;

    float *p_normed, *p_q, *p_k, *p_v, *p_attn, *p_h, *p_ss;
    cudaGetSymbolAddress((void**)&p_normed, g_normed);
    cudaGetSymbolAddress((void**)&p_q,    g_q);
    cudaGetSymbolAddress((void**)&p_k,    g_k);
    cudaGetSymbolAddress((void**)&p_v,    g_v);
    cudaGetSymbolAddress((void**)&p_attn, g_attn);
    cudaGetSymbolAddress((void**)&p_h,    g_h);
    cudaGetSymbolAddress((void**)&p_ss,   g_ss);
    cudaFuncSetAttribute(flash_kernel,
                         cudaFuncAttributeMaxDynamicSharedMemorySize, FA_SMEM);

    // 1. adaLN modulation vectors (both layers)
    ss_kernel<<<1024, 256>>>(cond, w_ad1, b_ad1, w_ad2, b_ad2, p_ss);
    // 2. normed1 = LN(x) * (1+scale1) + shift1
    adaln_kernel<<<MTOT, 256>>>(x, p_ss, p_normed);
    // 3. q, k, v projections
    gemm_kernel<false, false><<<dim3(8, 32), 256>>>(p_normed, wq, bq, nullptr, p_q, MTOT, HID, HID);
    gemm_kernel<false, false><<<dim3(8, 32), 256>>>(p_normed, wk, bk, nullptr, p_k, MTOT, HID, HID);
    gemm_kernel<false, false><<<dim3(8, 32), 256>>>(p_normed, wv, bv, nullptr, p_v, MTOT, HID, HID);
    // 4. attention
    flash_kernel<<<dim3(LSEQ / 128, NHEAD, BATCH), 256, FA_SMEM>>>(p_q, p_k, p_v, kpm, p_attn);
    // 5. x1 = x + attn @ wo^T + bo   (into d_out)
    gemm_kernel<false, true><<<dim3(8, 32), 256>>>(p_attn, wo, bo, x, out, MTOT, HID, HID);
    // 6. normed2 = LN(x1) * (1+scale2) + shift2
    adaln_kernel<<<MTOT, 256>>>(out, p_ss + BATCH * 2048, p_normed);
    // 7. h = gelu(normed2 @ w1^T + b1)
    gemm_kernel<true, false><<<dim3(32, 32), 256>>>(p_normed, w1, b1, nullptr, p_h, MTOT, MLPD, HID);
    // 8. out = x1 + h @ w2^T + b2   (in-place on d_out)
    gemm_kernel<false, true><<<dim3(8, 32), 256>>>(p_h, w2, b2, out, out, MTOT, HID, MLPD);
}

// round 4
// speedup vs baseline: 1.7408x; 1.7408x over previous
#include <cuda_runtime.h>
#include <cuda_bf16.h>
#include <cstdint>
#include <cstdio>

#define HID   1024
#define CDIM  1024
#define NHEAD 16
#define HDIM  64
#define LSEQ  2048
#define BATCH 2
#define MTOT  4096   // B*L
#define MLPD  4096

// ---------------- scratch (static device globals; no cudaMalloc allowed) ---
__device__ float g_normed[MTOT * HID];
__device__ float g_q[MTOT * HID];
__device__ float g_k[MTOT * HID];
__device__ float g_v[MTOT * HID];
__device__ float g_attn[MTOT * HID];
__device__ float g_h[MTOT * MLPD];
__device__ float g_ss[2 * BATCH * 2048];   // [layer][batch][2H]
// tf32-pre-rounded weights
__device__ float g_rwq[HID * HID];
__device__ float g_rwk[HID * HID];
__device__ float g_rwv[HID * HID];
__device__ float g_rwo[HID * HID];
__device__ float g_rw1[MLPD * HID];
__device__ float g_rw2[HID * MLPD];

// ---------------- helpers --------------------------------------------------
__device__ __forceinline__ float tf32r(float x) {
    uint32_t u;
    asm("cvt.rna.tf32.f32 %0, %1;" : "=r"(u) : "f"(x));
    return __uint_as_float(u);
}

__device__ __forceinline__ void mma8(float* d, const uint32_t* a, const uint32_t* b) {
    asm volatile(
        "mma.sync.aligned.m16n8k8.row.col.f32.tf32.tf32.f32 "
        "{%0,%1,%2,%3}, {%4,%5,%6,%7}, {%8,%9}, {%0,%1,%2,%3};\n"
        : "+f"(d[0]), "+f"(d[1]), "+f"(d[2]), "+f"(d[3])
        : "r"(a[0]), "r"(a[1]), "r"(a[2]), "r"(a[3]), "r"(b[0]), "r"(b[1]));
}

__device__ __forceinline__ void ldsm4(uint32_t* r, uint32_t addr) {
    asm volatile("ldmatrix.sync.aligned.m8n8.x4.shared.b16 {%0,%1,%2,%3}, [%4];"
        : "=r"(r[0]), "=r"(r[1]), "=r"(r[2]), "=r"(r[3]) : "r"(addr));
}

__device__ __forceinline__ void cpasync16(uint32_t dst, const void* src) {
    asm volatile("cp.async.cg.shared.global [%0], [%1], 16;" :: "r"(dst), "l"(src));
}

// ---------------- weight tf32 pre-rounding ---------------------------------
__global__ void __launch_bounds__(256) round_w_kernel(
    const float* __restrict__ wq, const float* __restrict__ wk,
    const float* __restrict__ wv, const float* __restrict__ wo,
    const float* __restrict__ w1, const float* __restrict__ w2,
    float* __restrict__ rq, float* __restrict__ rk,
    float* __restrict__ rv, float* __restrict__ ro,
    float* __restrict__ r1, float* __restrict__ r2)
{
    const int S = 262144; // 1M floats in float4 units
    int idx = blockIdx.x * 256 + threadIdx.x;  // 0 .. 3145727
    const float* s; float* d; int off;
    if      (idx <     S) { s = wq; d = rq; off = idx; }
    else if (idx < 2 * S) { s = wk; d = rk; off = idx - S; }
    else if (idx < 3 * S) { s = wv; d = rv; off = idx - 2 * S; }
    else if (idx < 4 * S) { s = wo; d = ro; off = idx - 3 * S; }
    else if (idx < 8 * S) { s = w1; d = r1; off = idx - 4 * S; }
    else                  { s = w2; d = r2; off = idx - 8 * S; }
    float4 v = ((const float4*)s)[off];
    v.x = tf32r(v.x); v.y = tf32r(v.y); v.z = tf32r(v.z); v.w = tf32r(v.w);
    ((float4*)d)[off] = v;
}

// ---------------- adaLN modulation: ss = cond @ W^T + b  (tiny) ------------
__global__ void __launch_bounds__(256) ss_kernel(
    const float* __restrict__ cond,
    const float* __restrict__ w1, const float* __restrict__ b1,
    const float* __restrict__ w2, const float* __restrict__ b2,
    float* __restrict__ ss)
{
    int warp = threadIdx.x >> 5, lane = threadIdx.x & 31;
    int gw = blockIdx.x * 8 + warp;           // 0..8191
    int layer = gw >> 12;
    int rem = gw & 4095;
    int b = rem >> 11;
    int row = rem & 2047;
    const float* W  = layer ? w2 : w1;
    const float* bv = layer ? b2 : b1;
    const float* c  = cond + b * CDIM;
    const float* wr = W + (size_t)row * CDIM;
    float s = 0.f;
    for (int k = lane; k < CDIM; k += 32) s += c[k] * wr[k];
    #pragma unroll
    for (int o = 16; o > 0; o >>= 1) s += __shfl_xor_sync(0xffffffffu, s, o);
    if (lane == 0) ss[layer * (BATCH * 2048) + b * 2048 + row] = s + bv[row];
}

// ---------------- LayerNorm * (1+scale) + shift (output tf32-rounded) ------
__global__ void __launch_bounds__(256) adaln_kernel(
    const float* __restrict__ x, const float* __restrict__ ss,
    float* __restrict__ out)
{
    int row = blockIdx.x;
    int b = row >> 11;
    const float* xr = x + (size_t)row * HID;
    float v[4];
    float s = 0.f, sq = 0.f;
    #pragma unroll
    for (int i = 0; i < 4; i++) {
        v[i] = xr[threadIdx.x + i * 256];
        s += v[i];
        sq += v[i] * v[i];
    }
    __shared__ float red[16];
    #pragma unroll
    for (int o = 16; o > 0; o >>= 1) {
        s  += __shfl_xor_sync(0xffffffffu, s,  o);
        sq += __shfl_xor_sync(0xffffffffu, sq, o);
    }
    int warp = threadIdx.x >> 5, lane = threadIdx.x & 31;
    if (lane == 0) { red[warp] = s; red[warp + 8] = sq; }
    __syncthreads();
    if (warp == 0) {
        float a  = lane < 8 ? red[lane] : 0.f;
        float c2 = lane < 8 ? red[lane + 8] : 0.f;
        #pragma unroll
        for (int o = 4; o > 0; o >>= 1) {
            a  += __shfl_xor_sync(0xffffffffu, a,  o);
            c2 += __shfl_xor_sync(0xffffffffu, c2, o);
        }
        if (lane == 0) { red[0] = a; red[1] = c2; }
    }
    __syncthreads();
    float mean = red[0] * (1.f / HID);
    float var  = red[1] * (1.f / HID) - mean * mean;
    float rs   = rsqrtf(var + 1e-5f);
    const float* sc = ss + b * 2048;
    #pragma unroll
    for (int i = 0; i < 4; i++) {
        int c = threadIdx.x + i * 256;
        out[(size_t)row * HID + c] =
            tf32r((v[i] - mean) * rs * (1.f + sc[c]) + sc[1024 + c]);
    }
}

// ---------------- pipelined TF32 GEMM: C = A @ B^T + bias (+resid)(gelu) ---
// A [M,K] row-major (pre-rounded tf32), B [N,K] row-major (pre-rounded).
// BM=BN=128, BK=32, 3-stage cp.async, XOR-swizzled smem, ldmatrix frags.
// blockIdx.z selects (B,bias,C) for fused QKV.
#define GSTAGES 3
#define GSMEM (GSTAGES * 8192 * 4)

template <bool GELU, bool RESID, bool ROUND>
__global__ void __launch_bounds__(256) gemm2(
    const float* __restrict__ A,
    const float* __restrict__ Bp0, const float* __restrict__ Bp1, const float* __restrict__ Bp2,
    const float* __restrict__ bias0, const float* __restrict__ bias1, const float* __restrict__ bias2,
    const float* __restrict__ R,
    float* __restrict__ C0, float* __restrict__ C1, float* __restrict__ C2,
    int M, int N, int K)
{
    extern __shared__ float sm[];
    int which = blockIdx.z;
    const float* B    = which == 0 ? Bp0   : (which == 1 ? Bp1   : Bp2);
    const float* bias = which == 0 ? bias0 : (which == 1 ? bias1 : bias2);
    float*       C    = which == 0 ? C0    : (which == 1 ? C1    : C2);

    int tid = threadIdx.x, warp = tid >> 5, lane = tid & 31;
    int bm = blockIdx.y * 128, bn = blockIdx.x * 128;
    int wm = (warp >> 1) * 32, wn = (warp & 1) * 64;

    float acc[2][8][4];
    #pragma unroll
    for (int i = 0; i < 2; i++)
        #pragma unroll
        for (int j = 0; j < 8; j++)
            #pragma unroll
            for (int e = 0; e < 4; e++) acc[i][j][e] = 0.f;

    int lr = tid >> 3;      // 0..31 row within 32-row group
    int gg = tid & 7;       // granule 0..7
    const float* Ag = A + (size_t)(bm + lr) * K + gg * 4;
    const float* Bg = B + (size_t)(bn + lr) * K + gg * 4;
    uint32_t smb = (uint32_t)__cvta_generic_to_shared(sm);
    uint32_t swz = ((gg ^ (lr & 7)) << 2);

    auto load_stage = [&](int s, int k0) {
        uint32_t sb = smb + (uint32_t)s * 8192u * 4u;
        #pragma unroll
        for (int i = 0; i < 4; i++) {
            int r = lr + i * 32;
            uint32_t da = sb + (uint32_t)(r * 32) * 4u + swz * 4u;
            cpasync16(da,          Ag + (size_t)i * 32 * K + k0);
            cpasync16(da + 16384u, Bg + (size_t)i * 32 * K + k0);
        }
    };

    auto compute_stage = [&](int s) {
        uint32_t base = smb + (uint32_t)s * 8192u * 4u;
        #pragma unroll
        for (int ks = 0; ks < 4; ks++) {
            uint32_t a[2][4], b[4][4];
            #pragma unroll
            for (int mt = 0; mt < 2; mt++) {
                int arow = wm + mt * 16 + ((lane >> 3) & 1) * 8 + (lane & 7);
                int gA = ks * 2 + (lane >> 4);
                ldsm4(a[mt], base + (uint32_t)(arow * 32 + ((gA ^ (arow & 7)) << 2)) * 4u);
            }
            #pragma unroll
            for (int p = 0; p < 4; p++) {
                int brow = wn + p * 16 + ((lane >> 4) << 3) + (lane & 7);
                int gB = ks * 2 + ((lane >> 3) & 1);
                ldsm4(b[p], base + 16384u + (uint32_t)(brow * 32 + ((gB ^ (brow & 7)) << 2)) * 4u);
            }
            #pragma unroll
            for (int p = 0; p < 4; p++) {
                mma8(acc[0][2 * p],     a[0], &b[p][0]);
                mma8(acc[1][2 * p],     a[1], &b[p][0]);
                mma8(acc[0][2 * p + 1], a[0], &b[p][2]);
                mma8(acc[1][2 * p + 1], a[1], &b[p][2]);
            }
        }
    };

    int KT = K >> 5;
    load_stage(0, 0);
    asm volatile("cp.async.commit_group;");
    load_stage(1, 32);
    asm volatile("cp.async.commit_group;");

    for (int kt = 0; kt < KT; kt++) {
        asm volatile("cp.async.wait_group 1;");
        __syncthreads();
        if (kt + 2 < KT) load_stage((kt + 2) % GSTAGES, (kt + 2) * 32);
        asm volatile("cp.async.commit_group;");
        compute_stage(kt % GSTAGES);
    }

    #pragma unroll
    for (int mt = 0; mt < 2; mt++) {
        int r0 = bm + wm + mt * 16 + (lane >> 2);
        #pragma unroll
        for (int nt = 0; nt < 8; nt++) {
            int cn = bn + wn + nt * 8 + (lane & 3) * 2;
            #pragma unroll
            for (int e = 0; e < 4; e++) {
                int r  = r0 + (e >= 2 ? 8 : 0);
                int cc = cn + (e & 1);
                float vv = acc[mt][nt][e] + bias[cc];
                if (RESID) vv += R[(size_t)r * N + cc];
                if (GELU)  vv = 0.5f * vv * (1.f + erff(vv * 0.70710678118f));
                if (ROUND) vv = tf32r(vv);
                C[(size_t)r * N + cc] = vv;
            }
        }
    }
}

// ---------------- flash attention ------------------------------------------
// grid (L/128, NH, B). 256 threads = 8 warps, each warp owns 16 q rows.
// q/k/v are pre-rounded tf32; P rounded before PV mma; output rounded.
#define QS_STR 68
#define VS_STR 72
#define PS_STR 132
#define FA_SMEM ((128 * QS_STR + 128 * QS_STR + 128 * VS_STR + 128 * PS_STR + 128) * 4)

__global__ void __launch_bounds__(256) flash_kernel(
    const float* __restrict__ Q, const float* __restrict__ Kb,
    const float* __restrict__ Vb, const unsigned char* __restrict__ msk,
    float* __restrict__ O)
{
    extern __shared__ float sm[];
    float* Qs = sm;                        // [128][68]
    float* Ks = Qs + 128 * QS_STR;         // [128][68]
    float* Vs = Ks + 128 * QS_STR;         // [128][72]
    float* Ps = Vs + 128 * VS_STR;         // [128][132]
    float* Mb = Ps + 128 * PS_STR;         // [128] mask bias
    int qb = blockIdx.x, h = blockIdx.y, b = blockIdx.z;
    int tid = threadIdx.x, warp = tid >> 5, lane = tid & 31;

    size_t base_q = ((size_t)(b * LSEQ + qb * 128)) * HID + h * HDIM;
    #pragma unroll
    for (int i = 0; i < 8; i++) {
        int idx = tid + i * 256;
        int row = idx >> 4, c4 = (idx & 15) * 4;
        *(float4*)&Qs[row * QS_STR + c4] =
            *(const float4*)(Q + base_q + (size_t)row * HID + c4);
    }

    float Oacc[8][4];
    #pragma unroll
    for (int i = 0; i < 8; i++)
        #pragma unroll
        for (int e = 0; e < 4; e++) Oacc[i][e] = 0.f;
    float mrow[2] = {-1e30f, -1e30f}, lrow[2] = {0.f, 0.f};

    for (int kb = 0; kb < LSEQ / 128; kb++) {
        size_t base_k = ((size_t)(b * LSEQ + kb * 128)) * HID + h * HDIM;
        #pragma unroll
        for (int i = 0; i < 8; i++) {
            int idx = tid + i * 256;
            int row = idx >> 4, c4 = (idx & 15) * 4;
            *(float4*)&Ks[row * QS_STR + c4] =
                *(const float4*)(Kb + base_k + (size_t)row * HID + c4);
            *(float4*)&Vs[row * VS_STR + c4] =
                *(const float4*)(Vb + base_k + (size_t)row * HID + c4);
        }
        if (tid < 128) Mb[tid] = msk[b * LSEQ + kb * 128 + tid] ? -1e30f : 0.f;
        __syncthreads();

        // S = Q @ K^T  (warp: 16 x 128)
        float sacc[16][4];
        #pragma unroll
        for (int i = 0; i < 16; i++)
            #pragma unroll
            for (int e = 0; e < 4; e++) sacc[i][e] = 0.f;

        #pragma unroll
        for (int ks = 0; ks < 8; ks++) {
            int c = ks * 8 + (lane & 3);
            int r = warp * 16 + (lane >> 2);
            uint32_t af[4];
            af[0] = __float_as_uint(Qs[r * QS_STR + c]);
            af[1] = __float_as_uint(Qs[(r + 8) * QS_STR + c]);
            af[2] = __float_as_uint(Qs[r * QS_STR + c + 4]);
            af[3] = __float_as_uint(Qs[(r + 8) * QS_STR + c + 4]);
            #pragma unroll
            for (int nt = 0; nt < 16; nt++) {
                int n = nt * 8 + (lane >> 2);
                uint32_t bf[2];
                bf[0] = __float_as_uint(Ks[n * QS_STR + c]);
                bf[1] = __float_as_uint(Ks[n * QS_STR + c + 4]);
                mma8(sacc[nt], af, bf);
            }
        }

        // online softmax per row (j=0: row r, j=1: row r+8)
        #pragma unroll
        for (int j = 0; j < 2; j++) {
            float tmax = -1e30f;
            #pragma unroll
            for (int nt = 0; nt < 16; nt++) {
                #pragma unroll
                for (int e = 0; e < 2; e++) {
                    int kc = nt * 8 + (lane & 3) * 2 + e;
                    float sv = sacc[nt][j * 2 + e] * 0.125f + Mb[kc];
                    sacc[nt][j * 2 + e] = sv;
                    tmax = fmaxf(tmax, sv);
                }
            }
            tmax = fmaxf(tmax, __shfl_xor_sync(0xffffffffu, tmax, 1));
            tmax = fmaxf(tmax, __shfl_xor_sync(0xffffffffu, tmax, 2));
            float mnew  = fmaxf(mrow[j], tmax);
            float alpha = __expf(mrow[j] - mnew);
            mrow[j] = mnew;
            float psum = 0.f;
            int rl = warp * 16 + (lane >> 2) + j * 8;
            #pragma unroll
            for (int nt = 0; nt < 16; nt++) {
                #pragma unroll
                for (int e = 0; e < 2; e++) {
                    float p = __expf(sacc[nt][j * 2 + e] - mnew);
                    psum += p;
                    Ps[rl * PS_STR + nt * 8 + (lane & 3) * 2 + e] = tf32r(p);
                }
            }
            psum += __shfl_xor_sync(0xffffffffu, psum, 1);
            psum += __shfl_xor_sync(0xffffffffu, psum, 2);
            lrow[j] = lrow[j] * alpha + psum;
            #pragma unroll
            for (int nt = 0; nt < 8; nt++) {
                Oacc[nt][j * 2]     *= alpha;
                Oacc[nt][j * 2 + 1] *= alpha;
            }
        }
        __syncwarp();

        // O += P @ V  (warp: 16 x 64, K=128)
        #pragma unroll
        for (int ks = 0; ks < 16; ks++) {
            int c = ks * 8 + (lane & 3);
            int r = warp * 16 + (lane >> 2);
            uint32_t af[4];
            af[0] = __float_as_uint(Ps[r * PS_STR + c]);
            af[1] = __float_as_uint(Ps[(r + 8) * PS_STR + c]);
            af[2] = __float_as_uint(Ps[r * PS_STR + c + 4]);
            af[3] = __float_as_uint(Ps[(r + 8) * PS_STR + c + 4]);
            #pragma unroll
            for (int nt = 0; nt < 8; nt++) {
                uint32_t bf[2];
                bf[0] = __float_as_uint(Vs[c * VS_STR + nt * 8 + (lane >> 2)]);
                bf[1] = __float_as_uint(Vs[(c + 4) * VS_STR + nt * 8 + (lane >> 2)]);
                mma8(Oacc[nt], af, bf);
            }
        }
        __syncthreads();
    }

    #pragma unroll
    for (int j = 0; j < 2; j++) {
        float inv = 1.f / lrow[j];
        int row = qb * 128 + warp * 16 + (lane >> 2) + j * 8;
        size_t ob = ((size_t)(b * LSEQ + row)) * HID + h * HDIM;
        #pragma unroll
        for (int nt = 0; nt < 8; nt++) {
            int cc = nt * 8 + (lane & 3) * 2;
            O[ob + cc]     = tf32r(Oacc[nt][j * 2] * inv);
            O[ob + cc + 1] = tf32r(Oacc[nt][j * 2 + 1] * inv);
        }
    }
}

// ---------------- launch ----------------------------------------------------
extern "C" void kernel_launch(void* const* d_in, const int* in_sizes, int n_in,
                              void* d_out, int out_size)
{
    const float* x    = (const float*)d_in[0];
    const float* cond = (const float*)d_in[1];
    const unsigned char* kpm = (const unsigned char*)d_in[2];
    const float* w_ad1 = (const float*)d_in[3];
    const float* b_ad1 = (const float*)d_in[4];
    const float* w_ad2 = (const float*)d_in[5];
    const float* b_ad2 = (const float*)d_in[6];
    const float* wq = (const float*)d_in[7];
    const float* bq = (const float*)d_in[8];
    const float* wk = (const float*)d_in[9];
    const float* bk = (const float*)d_in[10];
    const float* wv = (const float*)d_in[11];
    const float* bv = (const float*)d_in[12];
    const float* wo = (const float*)d_in[13];
    const float* bo = (const float*)d_in[14];
    const float* w1 = (const float*)d_in[15];
    const float* b1 = (const float*)d_in[16];
    const float* w2 = (const float*)d_in[17];
    const float* b2 = (const float*)d_in[18];
    float* out = (float*)d_out;

    float *p_normed, *p_q, *p_k, *p_v, *p_attn, *p_h, *p_ss;
    float *p_rwq, *p_rwk, *p_rwv, *p_rwo, *p_rw1, *p_rw2;
    cudaGetSymbolAddress((void**)&p_normed, g_normed);
    cudaGetSymbolAddress((void**)&p_q,    g_q);
    cudaGetSymbolAddress((void**)&p_k,    g_k);
    cudaGetSymbolAddress((void**)&p_v,    g_v);
    cudaGetSymbolAddress((void**)&p_attn, g_attn);
    cudaGetSymbolAddress((void**)&p_h,    g_h);
    cudaGetSymbolAddress((void**)&p_ss,   g_ss);
    cudaGetSymbolAddress((void**)&p_rwq,  g_rwq);
    cudaGetSymbolAddress((void**)&p_rwk,  g_rwk);
    cudaGetSymbolAddress((void**)&p_rwv,  g_rwv);
    cudaGetSymbolAddress((void**)&p_rwo,  g_rwo);
    cudaGetSymbolAddress((void**)&p_rw1,  g_rw1);
    cudaGetSymbolAddress((void**)&p_rw2,  g_rw2);

    cudaFuncSetAttribute(flash_kernel,
                         cudaFuncAttributeMaxDynamicSharedMemorySize, FA_SMEM);
    cudaFuncSetAttribute(gemm2<false, false, true>,
                         cudaFuncAttributeMaxDynamicSharedMemorySize, GSMEM);
    cudaFuncSetAttribute(gemm2<false, true, false>,
                         cudaFuncAttributeMaxDynamicSharedMemorySize, GSMEM);
    cudaFuncSetAttribute(gemm2<true, false, true>,
                         cudaFuncAttributeMaxDynamicSharedMemorySize, GSMEM);

    // 0. round weights to tf32 once per call
    round_w_kernel<<<12288, 256>>>(wq, wk, wv, wo, w1, w2,
                                   p_rwq, p_rwk, p_rwv, p_rwo, p_rw1, p_rw2);
    // 1. adaLN modulation vectors (both layers)
    ss_kernel<<<1024, 256>>>(cond, w_ad1, b_ad1, w_ad2, b_ad2, p_ss);
    // 2. normed1 = LN(x) * (1+scale1) + shift1  (tf32-rounded)
    adaln_kernel<<<MTOT, 256>>>(x, p_ss, p_normed);
    // 3. fused q, k, v projections (outputs tf32-rounded for flash)
    gemm2<false, false, true><<<dim3(8, 32, 3), 256, GSMEM>>>(
        p_normed, p_rwq, p_rwk, p_rwv, bq, bk, bv, nullptr,
        p_q, p_k, p_v, MTOT, HID, HID);
    // 4. attention
    flash_kernel<<<dim3(LSEQ / 128, NHEAD, BATCH), 256, FA_SMEM>>>(
        p_q, p_k, p_v, kpm, p_attn);
    // 5. x1 = x + attn @ wo^T + bo   (into d_out)
    gemm2<false, true, false><<<dim3(8, 32, 1), 256, GSMEM>>>(
        p_attn, p_rwo, p_rwo, p_rwo, bo, bo, bo, x,
        out, out, out, MTOT, HID, HID);
    // 6. normed2 = LN(x1) * (1+scale2) + shift2
    adaln_kernel<<<MTOT, 256>>>(out, p_ss + BATCH * 2048, p_normed);
    // 7. h = gelu(normed2 @ w1^T + b1)  (tf32-rounded)
    gemm2<true, false, true><<<dim3(32, 32, 1), 256, GSMEM>>>(
        p_normed, p_rw1, p_rw1, p_rw1, b1, b1, b1, nullptr,
        p_h, p_h, p_h, MTOT, MLPD, HID);
    // 8. out = x1 + h @ w2^T + b2   (in-place on d_out)
    gemm2<false, true, false><<<dim3(8, 32, 1), 256, GSMEM>>>(
        p_h, p_rw2, p_rw2, p_rw2, b2, b2, b2, out,
        out, out, out, MTOT, HID, MLPD);
}